// round 7
// baseline (speedup 1.0000x reference)
#include <cuda_runtime.h>

// FiringRateModel: T-step scalar-feedback linear recurrence, B independent chains.
//
// State V = D^2∘u (u = v.*w/100), so the lag-2-deferred reduction is a PLAIN
// add tree (no muls):
//   V(t)  = D∘V(t-1) + c_t*D2A + f(t-1)*D2B          (wide, 3 f2-ops/pair)
//   S2(t) = sum(V(t))                                 (7 f2add + 2 shfl, used t+2)
//   z(t)  = S2(t-2) + c_t*SA + c_{t-1}*SDA + f(t-1)*SB + f(t-2)*SDB - gb
//   f(t)  = max(0, 200 - 400/(1 + 2^(K*poly(z))))     (== relu(200*tanh(poly)))
//
// ILP: C=2 chains per thread (chain, chain+B/2): two independent serial chains
// interleave inside one warp, filling MUFU/FMA stall cycles without TLP.
// R=4 lanes/chain, 16384 threads = 512 warps, TPB=128, grid=128 -> 1 warp/SMSP.

#define TPB 128

typedef unsigned long long u64p;

__device__ __forceinline__ u64p pk2(float lo, float hi) {
    u64p r;
    asm("mov.b64 %0, {%1,%2};" : "=l"(r) : "r"(__float_as_uint(lo)), "r"(__float_as_uint(hi)));
    return r;
}
__device__ __forceinline__ void upk2(u64p v, float &lo, float &hi) {
    unsigned int l, h;
    asm("mov.b64 {%0,%1}, %2;" : "=r"(l), "=r"(h) : "l"(v));
    lo = __uint_as_float(l); hi = __uint_as_float(h);
}
__device__ __forceinline__ u64p f2fma(u64p a, u64p b, u64p c) {
    u64p d;
    asm("fma.rn.f32x2 %0, %1, %2, %3;" : "=l"(d) : "l"(a), "l"(b), "l"(c));
    return d;
}
__device__ __forceinline__ u64p f2mul(u64p a, u64p b) {
    u64p d;
    asm("mul.rn.f32x2 %0, %1, %2;" : "=l"(d) : "l"(a), "l"(b));
    return d;
}
__device__ __forceinline__ u64p f2add(u64p a, u64p b) {
    u64p d;
    asm("add.rn.f32x2 %0, %1, %2;" : "=l"(d) : "l"(a), "l"(b));
    return d;
}
__device__ __forceinline__ float ex2a(float x) {
    float r; asm("ex2.approx.f32 %0, %1;" : "=f"(r) : "f"(x)); return r;
}
__device__ __forceinline__ float rcpa(float x) {
    float r; asm("rcp.approx.f32 %0, %1;" : "=f"(r) : "f"(x)); return r;
}

__global__ void __launch_bounds__(TPB, 1)
fr_kernel(const float* __restrict__ cur,   // [T, B]
          const float* __restrict__ fs0,   // [B]
          const float* __restrict__ av,    // [N]
          const float* __restrict__ bv,    // [N]
          const float* __restrict__ wv,    // [N]
          const float* __restrict__ dsv,   // [N]
          const float* __restrict__ pc,    // [6]
          const float* __restrict__ gbp,   // [1]
          float* __restrict__ out,         // [T, B]
          int T, int B)
{
    int tid = blockIdx.x * TPB + threadIdx.x;
    int halfB = B >> 1;
    int slot = tid >> 2;         // chain slot: handles chains slot and slot+halfB
    int r = tid & 3;
    if (slot >= halfB) return;
    int nb = r * 16;             // 16 neurons = 8 packed pairs per lane

    // Polynomial coefficients, squared per reference, K = 2*log2(e) folded in.
    const float K = 2.885390081777927f;
    float C0 = K * pc[0] * pc[0], C1 = K * pc[1] * pc[1], C2 = K * pc[2] * pc[2];
    float C3 = K * pc[3] * pc[3], C4 = K * pc[4] * pc[4], C5 = K * pc[5] * pc[5];
    float gb = gbp[0] * 0.01f;

    // Per-lane constants (shared by both chains).
    // A' = a*w/100, B' = 10*b*w, D = 1-ds; D2A = D^2∘A', D2B = D^2∘B'.
    u64p D[8], D2A[8], D2B[8];
    float sap = 0.f, sbp = 0.f, sdap = 0.f, sdbp = 0.f;
    #pragma unroll
    for (int j = 0; j < 8; j++) {
        int n0 = nb + 2 * j;
        float w0 = wv[n0],            w1 = wv[n0 + 1];
        float d0 = 1.f - dsv[n0],     d1 = 1.f - dsv[n0 + 1];
        float a0 = av[n0] * w0 * 0.01f, a1 = av[n0 + 1] * w1 * 0.01f;
        float b0 = 10.f * bv[n0] * w0,  b1 = 10.f * bv[n0 + 1] * w1;
        D[j]   = pk2(d0, d1);
        D2A[j] = pk2(d0 * d0 * a0, d1 * d1 * a1);
        D2B[j] = pk2(d0 * d0 * b0, d1 * d1 * b1);
        sap  += a0 + a1;
        sbp  += b0 + b1;
        sdap += d0 * a0 + d1 * a1;
        sdbp += d0 * b0 + d1 * b1;
    }
    #pragma unroll
    for (int m = 1; m <= 2; m <<= 1) {
        sap  += __shfl_xor_sync(0xffffffffu, sap,  m);
        sbp  += __shfl_xor_sync(0xffffffffu, sbp,  m);
        sdap += __shfl_xor_sync(0xffffffffu, sdap, m);
        sdbp += __shfl_xor_sync(0xffffffffu, sdbp, m);
    }
    const float SA = sap, SB = sbp, SDA = sdap, SDB = sdbp;

    // Per-chain state (i = 0,1)
    u64p V0[8], V1[8];
    #pragma unroll
    for (int j = 0; j < 8; j++) { V0[j] = 0ull; V1[j] = 0ull; }

    float f1_0 = fs0[slot],        f1_1 = fs0[slot + halfB];
    float fx2_0 = 0.f,             fx2_1 = 0.f;
    float Wm1_0 = 0.f, Wm2_0 = 0.f, Wm1_1 = 0.f, Wm2_1 = 0.f;
    float clast_0 = 0.f,           clast_1 = 0.f;   // c_{t-1}

    const float* cp0 = cur + slot;
    const float* cp1 = cur + slot + halfB;
    const float* lp0 = cp0 + (size_t)8 * B;   // prefetch -> c_{t+8}
    const float* lp1 = cp1 + (size_t)8 * B;
    float* op0 = out + slot;
    float* op1 = out + slot + halfB;

    // Prefetch rings (raw currents only; c-terms computed inline off-path)
    float cb0[8], cb1[8];
    #pragma unroll
    for (int i = 0; i < 8; i++) {
        cb0[i] = cp0[(size_t)i * B];
        cb1[i] = cp1[(size_t)i * B];
    }

    // One step for one chain. Suffix-selected state via macro args.
    #define FR_STEP1(c, f1, fx2, Wm1, Wm2, clast, V, op)                       \
    {                                                                          \
        /* off-path scalar prep: base = Wm2 + c*SA + clast*SDA + fx2*SDB -gb */\
        float base = fmaf((c), SA, fmaf((clast), SDA, Wm2 - gb));              \
        base = fmaf((fx2), SDB, base);                                         \
        /* serial: x -> Estrin -> ex2 -> rcp -> fma -> max */                  \
        float x = fmaf((f1), SB, base);                                        \
        float x2 = x * x;                                                      \
        float x4 = x2 * x2;                                                    \
        float e01 = fmaf(C1, x, C0);                                           \
        float e23 = fmaf(C3, x, C2);                                           \
        float e45 = fmaf(C5, x, C4);                                           \
        float q = fmaf(x2, e23, e01);                                          \
        q = fmaf(x4, e45, q);                                                  \
        float e = ex2a(q);                                                     \
        float fn = fmaf(rcpa(e + 1.f), -400.f, 200.f);                         \
        fn = fmaxf(fn, 0.f);                                                   \
        /* wide: V(t) = D∘V + c*D2A + f1*D2B (independent of fn) */            \
        u64p c2 = pk2((c), (c));                                               \
        u64p f2r = pk2((f1), (f1));                                            \
        _Pragma("unroll")                                                      \
        for (int j = 0; j < 8; j++) {                                          \
            u64p t1 = f2fma(D2B[j], f2r, f2mul(D2A[j], c2));                   \
            V[j] = f2fma(D[j], V[j], t1);                                      \
        }                                                                      \
        /* plain-add tree: S2(t), consumed at t+2 */                           \
        u64p g0 = f2add(f2add(V[0], V[1]), f2add(V[2], V[3]));                 \
        u64p g1 = f2add(f2add(V[4], V[5]), f2add(V[6], V[7]));                 \
        u64p gt = f2add(g0, g1);                                               \
        float lo, hi; upk2(gt, lo, hi);                                        \
        float s = lo + hi;                                                     \
        s += __shfl_xor_sync(0xffffffffu, s, 1);                               \
        s += __shfl_xor_sync(0xffffffffu, s, 2);                               \
        Wm2 = Wm1;                                                             \
        Wm1 = s;                                                               \
        clast = (c);                                                           \
        if (r == 0) *(op) = fn;                                                \
        (op) += B;                                                             \
        fx2 = (f1);                                                            \
        f1 = fn;                                                               \
    }

    // Main loop: steps [0, T-8), refill rings at distance 8.
    for (int t = 0; t < T - 8; t += 8) {
        #pragma unroll
        for (int k = 0; k < 8; k++) {
            float c0 = cb0[k];
            float c1 = cb1[k];
            cb0[k] = *lp0; lp0 += B;
            cb1[k] = *lp1; lp1 += B;
            FR_STEP1(c0, f1_0, fx2_0, Wm1_0, Wm2_0, clast_0, V0, op0)
            FR_STEP1(c1, f1_1, fx2_1, Wm1_1, Wm2_1, clast_1, V1, op1)
        }
    }
    // Epilogue: last 8 steps, no loads.
    #pragma unroll
    for (int k = 0; k < 8; k++) {
        FR_STEP1(cb0[k], f1_0, fx2_0, Wm1_0, Wm2_0, clast_0, V0, op0)
        FR_STEP1(cb1[k], f1_1, fx2_1, Wm1_1, Wm2_1, clast_1, V1, op1)
    }
    #undef FR_STEP1
}

extern "C" void kernel_launch(void* const* d_in, const int* in_sizes, int n_in,
                              void* d_out, int out_size) {
    const float* cur = (const float*)d_in[0];   // currents [T*B]
    const float* fs0 = (const float*)d_in[1];   // [B]
    const float* av  = (const float*)d_in[2];   // [N]
    const float* bv  = (const float*)d_in[3];   // [N]
    const float* wv  = (const float*)d_in[4];   // [N,1]
    const float* dsv = (const float*)d_in[5];   // [N]
    const float* pc  = (const float*)d_in[6];   // [DEG+1]
    const float* gbp = (const float*)d_in[7];   // scalar

    int B = in_sizes[1];
    int T = in_sizes[0] / B;

    int threads = (B / 2) * 4;                  // 2 chains/thread, 4 lanes/chain
    int blocks = (threads + TPB - 1) / TPB;
    fr_kernel<<<blocks, TPB>>>(cur, fs0, av, bv, wv, dsv, pc, gbp,
                               (float*)d_out, T, B);
}

// round 8
// speedup vs baseline: 1.0518x; 1.0518x over previous
#include <cuda_runtime.h>

// FiringRateModel: T-step scalar-feedback linear recurrence, B independent chains.
//
// State V = D^2∘u (u = v.*w/100): lag-2-deferred reduction is a PLAIN add tree:
//   V(t)  = D∘V(t-1) + c_t*D2A + f(t-1)*D2B          (wide, 3 f2-ops/pair)
//   S2(t) = sum(V(t))                                 (3 f2add + 3 shfl, used t+2)
//   z(t)  = S2(t-2) + c_t*SA + c_{t-1}*SDA + f(t-1)*SB + f(t-2)*SDB - gb
//   f(t)  = max(0, 200 - 400/(1 + 2^(K*poly(z))))     (== relu(200*tanh(poly)))
//
// TLP: R=8 lanes/chain (4 f32x2 pairs/lane) -> 65536 threads = 2048 warps;
// TPB=512, grid=128 -> 4 warps per SMSP. Evidence R4-R7: per-warp issue is
// latency-capped at ~23%; per-SMSP issue scales with warp count, so 4 warps
// pushes the fma pipe (53% @ 2 warps) toward saturation.

#define TPB 512

typedef unsigned long long u64p;

__device__ __forceinline__ u64p pk2(float lo, float hi) {
    u64p r;
    asm("mov.b64 %0, {%1,%2};" : "=l"(r) : "r"(__float_as_uint(lo)), "r"(__float_as_uint(hi)));
    return r;
}
__device__ __forceinline__ void upk2(u64p v, float &lo, float &hi) {
    unsigned int l, h;
    asm("mov.b64 {%0,%1}, %2;" : "=r"(l), "=r"(h) : "l"(v));
    lo = __uint_as_float(l); hi = __uint_as_float(h);
}
__device__ __forceinline__ u64p f2fma(u64p a, u64p b, u64p c) {
    u64p d;
    asm("fma.rn.f32x2 %0, %1, %2, %3;" : "=l"(d) : "l"(a), "l"(b), "l"(c));
    return d;
}
__device__ __forceinline__ u64p f2mul(u64p a, u64p b) {
    u64p d;
    asm("mul.rn.f32x2 %0, %1, %2;" : "=l"(d) : "l"(a), "l"(b));
    return d;
}
__device__ __forceinline__ u64p f2add(u64p a, u64p b) {
    u64p d;
    asm("add.rn.f32x2 %0, %1, %2;" : "=l"(d) : "l"(a), "l"(b));
    return d;
}
__device__ __forceinline__ float ex2a(float x) {
    float r; asm("ex2.approx.f32 %0, %1;" : "=f"(r) : "f"(x)); return r;
}
__device__ __forceinline__ float rcpa(float x) {
    float r; asm("rcp.approx.f32 %0, %1;" : "=f"(r) : "f"(x)); return r;
}

__global__ void __launch_bounds__(TPB, 1)
fr_kernel(const float* __restrict__ cur,   // [T, B]
          const float* __restrict__ fs0,   // [B]
          const float* __restrict__ av,    // [N]
          const float* __restrict__ bv,    // [N]
          const float* __restrict__ wv,    // [N]
          const float* __restrict__ dsv,   // [N]
          const float* __restrict__ pc,    // [6]
          const float* __restrict__ gbp,   // [1]
          float* __restrict__ out,         // [T, B]
          int T, int B)
{
    int tid = blockIdx.x * TPB + threadIdx.x;
    int chain = tid >> 3;        // one chain per 8 lanes
    int r = tid & 7;
    if (chain >= B) return;
    int nb = r * 8;              // 8 neurons = 4 packed pairs per lane

    // Polynomial coefficients, squared per reference, K = 2*log2(e) folded in.
    const float K = 2.885390081777927f;
    float C0 = K * pc[0] * pc[0], C1 = K * pc[1] * pc[1], C2 = K * pc[2] * pc[2];
    float C3 = K * pc[3] * pc[3], C4 = K * pc[4] * pc[4], C5 = K * pc[5] * pc[5];
    float gb = gbp[0] * 0.01f;

    // Per-lane constants. A' = a*w/100, B' = 10*b*w, D = 1-ds.
    // D2A = D^2∘A', D2B = D^2∘B'.
    u64p D[4], D2A[4], D2B[4], V[4];
    float sap = 0.f, sbp = 0.f, sdap = 0.f, sdbp = 0.f;
    #pragma unroll
    for (int j = 0; j < 4; j++) {
        int n0 = nb + 2 * j;
        float w0 = wv[n0],            w1 = wv[n0 + 1];
        float d0 = 1.f - dsv[n0],     d1 = 1.f - dsv[n0 + 1];
        float a0 = av[n0] * w0 * 0.01f, a1 = av[n0 + 1] * w1 * 0.01f;
        float b0 = 10.f * bv[n0] * w0,  b1 = 10.f * bv[n0 + 1] * w1;
        D[j]   = pk2(d0, d1);
        D2A[j] = pk2(d0 * d0 * a0, d1 * d1 * a1);
        D2B[j] = pk2(d0 * d0 * b0, d1 * d1 * b1);
        V[j]   = 0ull;
        sap  += a0 + a1;
        sbp  += b0 + b1;
        sdap += d0 * a0 + d1 * a1;
        sdbp += d0 * b0 + d1 * b1;
    }
    #pragma unroll
    for (int m = 1; m <= 4; m <<= 1) {
        sap  += __shfl_xor_sync(0xffffffffu, sap,  m);
        sbp  += __shfl_xor_sync(0xffffffffu, sbp,  m);
        sdap += __shfl_xor_sync(0xffffffffu, sdap, m);
        sdbp += __shfl_xor_sync(0xffffffffu, sdbp, m);
    }
    const float SA = sap, SB = sbp, SDA = sdap, SDB = sdbp;

    float f1 = fs0[chain];       // f(t-1)
    float fx2 = 0.f;             // f(t-2)
    float Wm1 = 0.f, Wm2 = 0.f;  // S2(t-1), S2(t-2)  (V(-1)=V(-2)=0)
    float clast = 0.f;           // c_{t-1}

    const float* cp = cur + chain;         // initial ring fill
    const float* lp = cp + (size_t)8 * B;  // prefetch pointer -> c_{t+8}
    float* op = out + chain;

    // Prefetch ring: cb[i] = c_i
    float cb[8];
    #pragma unroll
    for (int i = 0; i < 8; i++) cb[i] = cp[(size_t)i * B];

    // One recurrence step with c = c_t.
    #define FR_STEP(c)                                                         \
    {                                                                          \
        /* off-path scalar prep: base = Wm2 + c*SA + clast*SDA + fx2*SDB-gb */ \
        float base = fmaf((c), SA, fmaf(clast, SDA, Wm2 - gb));                \
        base = fmaf(fx2, SDB, base);                                           \
        /* serial: x -> Estrin -> ex2 -> rcp -> fma -> max */                  \
        float x = fmaf(f1, SB, base);                                          \
        float x2 = x * x;                                                      \
        float x4 = x2 * x2;                                                    \
        float e01 = fmaf(C1, x, C0);                                           \
        float e23 = fmaf(C3, x, C2);                                           \
        float e45 = fmaf(C5, x, C4);                                           \
        float q = fmaf(x2, e23, e01);                                          \
        q = fmaf(x4, e45, q);                          /* q = K*poly(x) */     \
        float e = ex2a(q);                                                     \
        float fn = fmaf(rcpa(e + 1.f), -400.f, 200.f);                         \
        fn = fmaxf(fn, 0.f);                                                   \
        /* wide: V(t) = D∘V + c*D2A + f1*D2B (independent of fn) */            \
        u64p c2 = pk2((c), (c));                                               \
        u64p f2r = pk2(f1, f1);                                                \
        _Pragma("unroll")                                                      \
        for (int j = 0; j < 4; j++) {                                          \
            u64p t1 = f2fma(D2B[j], f2r, f2mul(D2A[j], c2));                   \
            V[j] = f2fma(D[j], V[j], t1);                                      \
        }                                                                      \
        /* plain-add tree: S2(t), consumed at t+2 (2 periods of slack) */      \
        u64p gt = f2add(f2add(V[0], V[1]), f2add(V[2], V[3]));                 \
        float lo, hi; upk2(gt, lo, hi);                                        \
        float s = lo + hi;                                                     \
        s += __shfl_xor_sync(0xffffffffu, s, 1);                               \
        s += __shfl_xor_sync(0xffffffffu, s, 2);                               \
        s += __shfl_xor_sync(0xffffffffu, s, 4);                               \
        Wm2 = Wm1;                                                             \
        Wm1 = s;                                                               \
        clast = (c);                                                           \
        if (r == 0) *op = fn;                                                  \
        op += B;                                                               \
        fx2 = f1;                                                              \
        f1 = fn;                                                               \
    }

    // Main loop: steps [0, T-8), refill ring at distance 8
    for (int t = 0; t < T - 8; t += 8) {
        #pragma unroll
        for (int k = 0; k < 8; k++) {
            float c = cb[k];
            cb[k] = *lp; lp += B;
            FR_STEP(c)
        }
    }
    // Epilogue: last 8 steps, no loads
    #pragma unroll
    for (int k = 0; k < 8; k++) {
        FR_STEP(cb[k])
    }
    #undef FR_STEP
}

extern "C" void kernel_launch(void* const* d_in, const int* in_sizes, int n_in,
                              void* d_out, int out_size) {
    const float* cur = (const float*)d_in[0];   // currents [T*B]
    const float* fs0 = (const float*)d_in[1];   // [B]
    const float* av  = (const float*)d_in[2];   // [N]
    const float* bv  = (const float*)d_in[3];   // [N]
    const float* wv  = (const float*)d_in[4];   // [N,1]
    const float* dsv = (const float*)d_in[5];   // [N]
    const float* pc  = (const float*)d_in[6];   // [DEG+1]
    const float* gbp = (const float*)d_in[7];   // scalar

    int B = in_sizes[1];
    int T = in_sizes[0] / B;

    int threads = B * 8;                        // 8 lanes per chain
    int blocks = (threads + TPB - 1) / TPB;
    fr_kernel<<<blocks, TPB>>>(cur, fs0, av, bv, wv, dsv, pc, gbp,
                               (float*)d_out, T, B);
}

// round 9
// speedup vs baseline: 1.2820x; 1.2189x over previous
#include <cuda_runtime.h>

// FiringRateModel: T-step scalar-feedback linear recurrence, B independent chains.
//
// State V = D^2∘u (u = v.*w/100), lag-2 algebra:
//   V(t)  = D∘V(t-1) + c_t*D2A + f(t-1)*D2B          (wide, 3 f2-ops/pair)
//   S2(t) = sum(V(t))
//   z(t)  = S2(t-2) + c_t*SA + c_{t-1}*SDA + f(t-1)*SB + f(t-2)*SDB - gb
//   f(t)  = max(0, 200 - 400/(1 + 2^(K*poly(z))))     (== relu(200*tanh(poly)))
//
// KEY CHANGE vs R6/R8: the reduction is software-pipelined across the step
// boundary. The in-warp tree produces a scalar `pend` at the END of body t;
// the two dependent SHFL.XORs that complete the reduction run in body t+1
// (operand one full period old -> no issue stall). In-order issue previously
// blocked ~100 cyc/step on tree->shfl->shfl even though the value had lag-2
// slack -- deferring the CONSUMER isn't enough; the PRODUCER must move too.
//
// R=4 lanes/chain, TPB=256, grid=128 -> 2 warps/SMSP (best measured shape).

#define TPB 256

typedef unsigned long long u64p;

__device__ __forceinline__ u64p pk2(float lo, float hi) {
    u64p r;
    asm("mov.b64 %0, {%1,%2};" : "=l"(r) : "r"(__float_as_uint(lo)), "r"(__float_as_uint(hi)));
    return r;
}
__device__ __forceinline__ void upk2(u64p v, float &lo, float &hi) {
    unsigned int l, h;
    asm("mov.b64 {%0,%1}, %2;" : "=r"(l), "=r"(h) : "l"(v));
    lo = __uint_as_float(l); hi = __uint_as_float(h);
}
__device__ __forceinline__ u64p f2fma(u64p a, u64p b, u64p c) {
    u64p d;
    asm("fma.rn.f32x2 %0, %1, %2, %3;" : "=l"(d) : "l"(a), "l"(b), "l"(c));
    return d;
}
__device__ __forceinline__ u64p f2mul(u64p a, u64p b) {
    u64p d;
    asm("mul.rn.f32x2 %0, %1, %2;" : "=l"(d) : "l"(a), "l"(b));
    return d;
}
__device__ __forceinline__ u64p f2add(u64p a, u64p b) {
    u64p d;
    asm("add.rn.f32x2 %0, %1, %2;" : "=l"(d) : "l"(a), "l"(b));
    return d;
}
__device__ __forceinline__ float ex2a(float x) {
    float r; asm("ex2.approx.f32 %0, %1;" : "=f"(r) : "f"(x)); return r;
}
__device__ __forceinline__ float rcpa(float x) {
    float r; asm("rcp.approx.f32 %0, %1;" : "=f"(r) : "f"(x)); return r;
}

__global__ void __launch_bounds__(TPB, 1)
fr_kernel(const float* __restrict__ cur,   // [T, B]
          const float* __restrict__ fs0,   // [B]
          const float* __restrict__ av,    // [N]
          const float* __restrict__ bv,    // [N]
          const float* __restrict__ wv,    // [N]
          const float* __restrict__ dsv,   // [N]
          const float* __restrict__ pc,    // [6]
          const float* __restrict__ gbp,   // [1]
          float* __restrict__ out,         // [T, B]
          int T, int B)
{
    int tid = blockIdx.x * TPB + threadIdx.x;
    int chain = tid >> 2;        // one chain per 4 lanes
    int r = tid & 3;
    if (chain >= B) return;
    int nb = r * 16;             // 16 neurons = 8 packed pairs per lane

    // Polynomial coefficients, squared per reference, K = 2*log2(e) folded in.
    const float K = 2.885390081777927f;
    float C0 = K * pc[0] * pc[0], C1 = K * pc[1] * pc[1], C2 = K * pc[2] * pc[2];
    float C3 = K * pc[3] * pc[3], C4 = K * pc[4] * pc[4], C5 = K * pc[5] * pc[5];
    float gb = gbp[0] * 0.01f;

    // Per-lane constants. A' = a*w/100, B' = 10*b*w, D = 1-ds.
    // D2A = D^2∘A', D2B = D^2∘B'.
    u64p D[8], D2A[8], D2B[8], V[8];
    float sap = 0.f, sbp = 0.f, sdap = 0.f, sdbp = 0.f;
    #pragma unroll
    for (int j = 0; j < 8; j++) {
        int n0 = nb + 2 * j;
        float w0 = wv[n0],            w1 = wv[n0 + 1];
        float d0 = 1.f - dsv[n0],     d1 = 1.f - dsv[n0 + 1];
        float a0 = av[n0] * w0 * 0.01f, a1 = av[n0 + 1] * w1 * 0.01f;
        float b0 = 10.f * bv[n0] * w0,  b1 = 10.f * bv[n0 + 1] * w1;
        D[j]   = pk2(d0, d1);
        D2A[j] = pk2(d0 * d0 * a0, d1 * d1 * a1);
        D2B[j] = pk2(d0 * d0 * b0, d1 * d1 * b1);
        V[j]   = 0ull;
        sap  += a0 + a1;
        sbp  += b0 + b1;
        sdap += d0 * a0 + d1 * a1;
        sdbp += d0 * b0 + d1 * b1;
    }
    #pragma unroll
    for (int m = 1; m <= 2; m <<= 1) {
        sap  += __shfl_xor_sync(0xffffffffu, sap,  m);
        sbp  += __shfl_xor_sync(0xffffffffu, sbp,  m);
        sdap += __shfl_xor_sync(0xffffffffu, sdap, m);
        sdbp += __shfl_xor_sync(0xffffffffu, sdbp, m);
    }
    const float SA = sap, SB = sbp, SDA = sdap, SDB = sdbp;

    float f1 = fs0[chain];       // f(t-1)
    float fx2 = 0.f;             // f(t-2)
    float Wprev = 0.f;           // S2(t-2) at top of body t
    float pend = 0.f;            // in-lane tree sum of V(t-1), awaiting shfls

    const float* cp = cur + chain;         // initial ring fill
    const float* lp = cp + (size_t)8 * B;  // prefetch pointer -> c_{t+8}
    float* op = out + chain;

    // Prefetch rings: cb[i] = c_i (raw), cs[i] = c_i*SA + c_{i-1}*SDA - gb.
    float cb[8], cs[8];
    {
        float clast = 0.f;       // c_{-1} = 0
        #pragma unroll
        for (int i = 0; i < 8; i++) {
            cb[i] = cp[(size_t)i * B];
            cs[i] = fmaf(cb[i], SA, fmaf(clast, SDA, -gb));
            clast = cb[i];
        }
    }
    float clast = cb[7];

    // One step. craw = c_t, cpre = c_t*SA + c_{t-1}*SDA - gb.
    #define FR_STEP(craw, cpre)                                                \
    {                                                                          \
        /* 1. phi(t): z = Wprev(=S2(t-2)) + cpre + f(t-2)*SDB + f(t-1)*SB */   \
        float base = fmaf(fx2, SDB, Wprev + (cpre));                           \
        float x = fmaf(f1, SB, base);                                          \
        float x2 = x * x;                                                      \
        float x4 = x2 * x2;                                                    \
        float e01 = fmaf(C1, x, C0);                                           \
        float e23 = fmaf(C3, x, C2);                                           \
        float e45 = fmaf(C5, x, C4);                                           \
        float q = fmaf(x2, e23, e01);                                          \
        q = fmaf(x4, e45, q);                          /* q = K*poly(x) */     \
        float e = ex2a(q);                                                     \
        float fn = fmaf(rcpa(e + 1.f), -400.f, 200.f);                         \
        fn = fmaxf(fn, 0.f);                                                   \
        /* 2. wide: V(t) = D∘V + c*D2A + f1*D2B */                             \
        u64p c2 = pk2((craw), (craw));                                         \
        u64p f2r = pk2(f1, f1);                                                \
        _Pragma("unroll")                                                      \
        for (int j = 0; j < 8; j++) {                                          \
            u64p t1 = f2fma(D2B[j], f2r, f2mul(D2A[j], c2));                   \
            V[j] = f2fma(D[j], V[j], t1);                                      \
        }                                                                      \
        /* 3. shfl pair on LAST step's tree sum (operand 1 period old):    */  \
        /*    completes S2(t-1), consumed by phi(t+1) as its S2((t+1)-2).  */  \
        float sp = pend;                                                       \
        sp += __shfl_xor_sync(0xffffffffu, sp, 1);                             \
        sp += __shfl_xor_sync(0xffffffffu, sp, 2);                             \
        Wprev = sp;                                                            \
        /* 4. tree over V(t) -> pend (shfl'd NEXT body) */                     \
        u64p g0 = f2add(f2add(V[0], V[1]), f2add(V[2], V[3]));                 \
        u64p g1 = f2add(f2add(V[4], V[5]), f2add(V[6], V[7]));                 \
        u64p gt = f2add(g0, g1);                                               \
        float lo, hi; upk2(gt, lo, hi);                                        \
        pend = lo + hi;                                                        \
        /* 5. output + rotate */                                               \
        if (r == 0) *op = fn;                                                  \
        op += B;                                                               \
        fx2 = f1;                                                              \
        f1 = fn;                                                               \
    }

    // Main loop: steps [0, T-8), refill rings at distance 8
    for (int t = 0; t < T - 8; t += 8) {
        #pragma unroll
        for (int k = 0; k < 8; k++) {
            float craw = cb[k];
            float cpre = cs[k];
            float cnew = *lp; lp += B;
            cb[k] = cnew;
            cs[k] = fmaf(cnew, SA, fmaf(clast, SDA, -gb));
            clast = cnew;
            FR_STEP(craw, cpre)
        }
    }
    // Epilogue: last 8 steps, no loads
    #pragma unroll
    for (int k = 0; k < 8; k++) {
        FR_STEP(cb[k], cs[k])
    }
    #undef FR_STEP
}

extern "C" void kernel_launch(void* const* d_in, const int* in_sizes, int n_in,
                              void* d_out, int out_size) {
    const float* cur = (const float*)d_in[0];   // currents [T*B]
    const float* fs0 = (const float*)d_in[1];   // [B]
    const float* av  = (const float*)d_in[2];   // [N]
    const float* bv  = (const float*)d_in[3];   // [N]
    const float* wv  = (const float*)d_in[4];   // [N,1]
    const float* dsv = (const float*)d_in[5];   // [N]
    const float* pc  = (const float*)d_in[6];   // [DEG+1]
    const float* gbp = (const float*)d_in[7];   // scalar

    int B = in_sizes[1];
    int T = in_sizes[0] / B;

    int threads = B * 4;                        // 4 lanes per chain
    int blocks = (threads + TPB - 1) / TPB;
    fr_kernel<<<blocks, TPB>>>(cur, fs0, av, bv, wv, dsv, pc, gbp,
                               (float*)d_out, T, B);
}